// round 1
// baseline (speedup 1.0000x reference)
#include <cuda_runtime.h>
#include <cuda_bf16.h>
#include <math.h>

// Problem constants
#define T_TOK 2048
#define D_DIM 1024
#define F_DIM 4096
#define E_EXP 8
#define K_TOP 2

#define BM 64
#define BN 64
#define BK 16

// Scratch (static __device__ arrays: allocation-free per harness rules)
__device__ float g_h[(size_t)T_TOK * K_TOP * F_DIM];   // 4096 x 4096 fp32 = 64 MB
__device__ int   g_list[E_EXP * T_TOK];                // per-expert entry list (entry = t*2+k)
__device__ float g_wts[T_TOK * K_TOP];                 // gate prob per (t,k)
__device__ int   g_cnt[E_EXP];                         // entries per expert
__device__ int   g_top1[E_EXP];                        // top-1 counts (aux loss)
__device__ float g_psum[E_EXP];                        // sum of gate probs per expert

// ---------------------------------------------------------------------------
__global__ void zero_kernel(float* out, int out_size) {
    int stride = gridDim.x * blockDim.x;
    for (int i = blockIdx.x * blockDim.x + threadIdx.x; i < out_size; i += stride)
        out[i] = 0.0f;
    if (blockIdx.x == 0 && threadIdx.x < E_EXP) {
        g_cnt[threadIdx.x]  = 0;
        g_top1[threadIdx.x] = 0;
        g_psum[threadIdx.x] = 0.0f;
    }
}

// ---------------------------------------------------------------------------
// Gating: 1 block per token, 8 warps -> 8 logits, thread 0 softmax + top-2.
__global__ void gate_kernel(const float* __restrict__ x,
                            const float* __restrict__ Wg,
                            const float* __restrict__ bg) {
    int t = blockIdx.x;
    int w = threadIdx.x >> 5;
    int lane = threadIdx.x & 31;
    const float* xr = x + (size_t)t * D_DIM;

    float s = 0.0f;
    for (int d = lane; d < D_DIM; d += 32)
        s += xr[d] * Wg[d * E_EXP + w];
    #pragma unroll
    for (int o = 16; o; o >>= 1) s += __shfl_xor_sync(0xffffffffu, s, o);

    __shared__ float lg[E_EXP];
    if (lane == 0) lg[w] = s + bg[w];
    __syncthreads();

    if (threadIdx.x == 0) {
        float mx = lg[0];
        #pragma unroll
        for (int e = 1; e < E_EXP; e++) mx = fmaxf(mx, lg[e]);
        float p[E_EXP];
        float sum = 0.0f;
        #pragma unroll
        for (int e = 0; e < E_EXP; e++) { p[e] = __expf(lg[e] - mx); sum += p[e]; }
        float inv = 1.0f / sum;
        #pragma unroll
        for (int e = 0; e < E_EXP; e++) { p[e] *= inv; atomicAdd(&g_psum[e], p[e]); }

        // top-1 (ties -> lowest index, like jax.lax.top_k)
        int i0 = 0;
        #pragma unroll
        for (int e = 1; e < E_EXP; e++) if (p[e] > p[i0]) i0 = e;
        // top-2
        int i1 = -1;
        #pragma unroll
        for (int e = 0; e < E_EXP; e++) {
            if (e == i0) continue;
            if (i1 < 0 || p[e] > p[i1]) i1 = e;
        }
        atomicAdd(&g_top1[i0], 1);

        int pos0 = atomicAdd(&g_cnt[i0], 1);
        g_list[i0 * T_TOK + pos0] = t * 2 + 0;
        g_wts[t * 2 + 0] = p[i0];
        int pos1 = atomicAdd(&g_cnt[i1], 1);
        g_list[i1 * T_TOK + pos1] = t * 2 + 1;
        g_wts[t * 2 + 1] = p[i1];
    }
}

// ---------------------------------------------------------------------------
__global__ void aux_kernel(float* out, int out_size) {
    if (threadIdx.x == 0 && blockIdx.x == 0) {
        float aux = 0.0f;
        #pragma unroll
        for (int e = 0; e < E_EXP; e++)
            aux += ((float)g_top1[e] / ((float)T_TOK + 1e-8f)) *
                   (g_psum[e] / (float)T_TOK);
        aux *= (float)E_EXP;
        if (out_size > T_TOK * D_DIM) out[T_TOK * D_DIM] = aux;
    }
}

// ---------------------------------------------------------------------------
// Grouped GEMM 1: h[entry, f] = relu( x[t] @ W1[e] + b1[e] )
// grid (T/BM, F/BN, E). Gathered A rows via g_list.
__global__ __launch_bounds__(256)
void gemm1_kernel(const float* __restrict__ x,
                  const float* __restrict__ W1,
                  const float* __restrict__ b1) {
    int e = blockIdx.z;
    int n = g_cnt[e];
    int m0 = blockIdx.x * BM;
    if (m0 >= n) return;
    int f0 = blockIdx.y * BN;

    __shared__ float As[BK][BM];
    __shared__ float Bs[BK][BN];

    int tid = threadIdx.x;
    int tx = tid & 15, ty = tid >> 4;

    // A-tile loader mapping: 64 rows x 16 cols, 4 floats per thread
    int lr = tid >> 2;            // row within tile
    int lc = (tid & 3) * 4;       // col (k) within tile
    const float* arow = nullptr;
    if (m0 + lr < n) {
        int entry = g_list[e * T_TOK + m0 + lr];
        arow = x + (size_t)(entry >> 1) * D_DIM;
    }
    // B-tile loader: 16 rows x 64 cols
    int brow = tid >> 4;
    int bcol = (tid & 15) * 4;
    const float* Bbase = W1 + (size_t)e * D_DIM * F_DIM + f0;

    float acc[4][4] = {};
    for (int kk = 0; kk < D_DIM; kk += BK) {
        float4 av = make_float4(0.f, 0.f, 0.f, 0.f);
        if (arow) av = *(const float4*)(arow + kk + lc);
        As[lc + 0][lr] = av.x; As[lc + 1][lr] = av.y;
        As[lc + 2][lr] = av.z; As[lc + 3][lr] = av.w;
        *(float4*)&Bs[brow][bcol] =
            *(const float4*)(Bbase + (size_t)(kk + brow) * F_DIM + bcol);
        __syncthreads();
        #pragma unroll
        for (int k = 0; k < BK; k++) {
            float4 a = *(const float4*)&As[k][ty * 4];
            float4 b = *(const float4*)&Bs[k][tx * 4];
            float ar[4] = {a.x, a.y, a.z, a.w};
            float br[4] = {b.x, b.y, b.z, b.w};
            #pragma unroll
            for (int i = 0; i < 4; i++)
                #pragma unroll
                for (int j = 0; j < 4; j++)
                    acc[i][j] = fmaf(ar[i], br[j], acc[i][j]);
        }
        __syncthreads();
    }

    #pragma unroll
    for (int i = 0; i < 4; i++) {
        int r = m0 + ty * 4 + i;
        if (r >= n) continue;
        int entry = g_list[e * T_TOK + r];
        float* hrow = g_h + (size_t)entry * F_DIM + f0 + tx * 4;
        float4 v;
        v.x = fmaxf(acc[i][0] + b1[e * F_DIM + f0 + tx * 4 + 0], 0.f);
        v.y = fmaxf(acc[i][1] + b1[e * F_DIM + f0 + tx * 4 + 1], 0.f);
        v.z = fmaxf(acc[i][2] + b1[e * F_DIM + f0 + tx * 4 + 2], 0.f);
        v.w = fmaxf(acc[i][3] + b1[e * F_DIM + f0 + tx * 4 + 3], 0.f);
        *(float4*)hrow = v;
    }
}

// ---------------------------------------------------------------------------
// Grouped GEMM 2: y = h @ W2[e] + b2[e]; out[t] += wt * y  (atomicAdd, exactly
// 2 commutative contributions per element -> deterministic).
// grid (T/BM, D/BN, E)
__global__ __launch_bounds__(256)
void gemm2_kernel(const float* __restrict__ W2,
                  const float* __restrict__ b2,
                  float* __restrict__ out) {
    int e = blockIdx.z;
    int n = g_cnt[e];
    int m0 = blockIdx.x * BM;
    if (m0 >= n) return;
    int d0 = blockIdx.y * BN;

    __shared__ float As[BK][BM];
    __shared__ float Bs[BK][BN];

    int tid = threadIdx.x;
    int tx = tid & 15, ty = tid >> 4;

    int lr = tid >> 2;
    int lc = (tid & 3) * 4;
    const float* arow = nullptr;
    if (m0 + lr < n) {
        int entry = g_list[e * T_TOK + m0 + lr];
        arow = g_h + (size_t)entry * F_DIM;
    }
    int brow = tid >> 4;
    int bcol = (tid & 15) * 4;
    const float* Bbase = W2 + (size_t)e * F_DIM * D_DIM + d0;

    float acc[4][4] = {};
    for (int kk = 0; kk < F_DIM; kk += BK) {
        float4 av = make_float4(0.f, 0.f, 0.f, 0.f);
        if (arow) av = *(const float4*)(arow + kk + lc);
        As[lc + 0][lr] = av.x; As[lc + 1][lr] = av.y;
        As[lc + 2][lr] = av.z; As[lc + 3][lr] = av.w;
        *(float4*)&Bs[brow][bcol] =
            *(const float4*)(Bbase + (size_t)(kk + brow) * D_DIM + bcol);
        __syncthreads();
        #pragma unroll
        for (int k = 0; k < BK; k++) {
            float4 a = *(const float4*)&As[k][ty * 4];
            float4 b = *(const float4*)&Bs[k][tx * 4];
            float ar[4] = {a.x, a.y, a.z, a.w};
            float br[4] = {b.x, b.y, b.z, b.w};
            #pragma unroll
            for (int i = 0; i < 4; i++)
                #pragma unroll
                for (int j = 0; j < 4; j++)
                    acc[i][j] = fmaf(ar[i], br[j], acc[i][j]);
        }
        __syncthreads();
    }

    #pragma unroll
    for (int i = 0; i < 4; i++) {
        int r = m0 + ty * 4 + i;
        if (r >= n) continue;
        int entry = g_list[e * T_TOK + r];
        int t = entry >> 1;
        float wt = g_wts[entry];
        float* orow = out + (size_t)t * D_DIM + d0 + tx * 4;
        #pragma unroll
        for (int j = 0; j < 4; j++) {
            float v = acc[i][j] + b2[e * D_DIM + d0 + tx * 4 + j];
            atomicAdd(&orow[j], wt * v);
        }
    }
}

// ---------------------------------------------------------------------------
extern "C" void kernel_launch(void* const* d_in, const int* in_sizes, int n_in,
                              void* d_out, int out_size) {
    const float* x  = (const float*)d_in[0];
    const float* Wg = (const float*)d_in[1];
    const float* bg = (const float*)d_in[2];
    const float* W1 = (const float*)d_in[3];
    const float* b1 = (const float*)d_in[4];
    const float* W2 = (const float*)d_in[5];
    const float* b2 = (const float*)d_in[6];
    float* out = (float*)d_out;

    zero_kernel<<<256, 256>>>(out, out_size);
    gate_kernel<<<T_TOK, 256>>>(x, Wg, bg);
    aux_kernel<<<1, 32>>>(out, out_size);

    dim3 g1(T_TOK / BM, F_DIM / BN, E_EXP);
    gemm1_kernel<<<g1, 256>>>(x, W1, b1);

    dim3 g2(T_TOK / BM, D_DIM / BN, E_EXP);
    gemm2_kernel<<<g2, 256>>>(W2, b2, out);
}